// round 6
// baseline (speedup 1.0000x reference)
#include <cuda_runtime.h>
#include <math.h>

#define MM      8
#define AA      48
#define NSPEC   4
#define NPAIRCH 10
#define NSHFR   16
#define RADDIM  (NSPEC * NSHFR)            /* 64  */
#define ANGDIM  (NPAIRCH * 32)             /* 320 */
#define OUTDIM  (RADDIM + ANGDIM)          /* 384 */
#define RCR_F   5.2f
#define RCA_F   3.5f
#define PI_F    3.14159265358979323846f
#define NT      512
#define NWARPS  (NT / 32)
#define EPB     8                           /* environments per block */
#define NBLK    (MM * AA / EPB)             /* 48 blocks */

__global__ __launch_bounds__(NT, 1) void aev_kernel(
    const float* __restrict__ coords,   // (M, A, 3)
    const float* __restrict__ EtaR,     // (1,)
    const float* __restrict__ ShfR,     // (16,)
    const float* __restrict__ EtaA,     // (1,)
    const float* __restrict__ Zeta,     // (1,)
    const float* __restrict__ ShfA,     // (4,)
    const float* __restrict__ ShfZ,     // (8,)
    const int*   __restrict__ species,  // (M, A)
    const int*   __restrict__ triu,     // (4, 4)
    float*       __restrict__ out)      // (M, A, 384)
{
    __shared__ float4 atm[AA];                  // x,y,z,species(bits) — one molecule
    __shared__ float4 nbrA[EPB][AA];            // ux,uy,uz,d (RCA neighbors per env)
    __shared__ float2 nbrB[EPB][AA];            // fc_A, species(bits)
    __shared__ float  sdd[EPB][AA];             // d  (radial)
    __shared__ float  spre[EPB][AA];            // 0.25*fc_R (0 if invalid)
    __shared__ int    ncnt[EPB];                // angular neighbor counts
    __shared__ int    eoff[EPB + 1];            // pooled pair offsets
    __shared__ float  rad[EPB][RADDIM];
    __shared__ float  ang[EPB][ANGDIM];
    __shared__ int    s_triu[NSPEC * NSPEC];

    const int b    = blockIdx.x;                // 0..47
    const int m    = b / (AA / EPB);            // molecule
    const int i0   = (b % (AA / EPB)) * EPB;    // first center atom of this block
    const int tid  = threadIdx.x;
    const int wid  = tid >> 5;
    const int lane = tid & 31;

    // per-lane parameters (L1/L2 cached tiny loads)
    const float etaR   = __ldg(EtaR);
    const float etaA   = __ldg(EtaA);
    const float zeta   = __ldg(Zeta);
    const float shfr_r = __ldg(&ShfR[lane & 15]);
    const float sha    = __ldg(&ShfA[lane >> 3]);
    const float shz    = __ldg(&ShfZ[lane & 7]);
    const float cz = __cosf(shz), sz = __sinf(shz);
    const bool  z32 = (zeta == 32.0f);

    // ---- phase 1: load molecule + zero accumulators ----
    if (tid < EPB) ncnt[tid] = 0;
    if (tid < NSPEC * NSPEC) s_triu[tid] = triu[tid];
    if (tid < AA) {
        const float* c = coords + (m * AA + tid) * 3;
        atm[tid] = make_float4(c[0], c[1], c[2],
                               __int_as_float(species[m * AA + tid]));
    }
    #pragma unroll
    for (int t = tid; t < EPB * RADDIM; t += NT) ((float*)rad)[t] = 0.0f;
    #pragma unroll
    for (int t = tid; t < EPB * ANGDIM; t += NT) ((float*)ang)[t] = 0.0f;
    __syncthreads();

    // ---- phase 2: distances + per-env neighbor compaction (384 items) ----
    if (tid < EPB * AA) {
        int e = tid / AA;
        int j = tid - e * AA;
        int i = i0 + e;
        float4 aj = atm[j];
        float4 ai = atm[i];
        int   spj = __float_as_int(aj.w);
        int   spi = __float_as_int(ai.w);
        float dx = aj.x - ai.x, dy = aj.y - ai.y, dz = aj.z - ai.z;
        float d2 = dx * dx + dy * dy + dz * dz;
        float d  = sqrtf(d2 > 0.0f ? d2 : 1.0f);
        bool pvb = (spi >= 0) && (spj >= 0) && (j != i);
        float pr = 0.0f;
        if (pvb && d <= RCR_F)
            pr = 0.25f * (0.5f * __cosf(d * (PI_F / RCR_F)) + 0.5f);
        sdd[e][j]  = d;
        spre[e][j] = pr;
        if (pvb && d <= RCA_F) {
            int   idx  = atomicAdd(&ncnt[e], 1);
            float rinv = 1.0f / d;
            nbrA[e][idx] = make_float4(dx * rinv, dy * rinv, dz * rinv, d);
            nbrB[e][idx] = make_float2(0.5f * __cosf(d * (PI_F / RCA_F)) + 0.5f, aj.w);
        }
    }
    __syncthreads();

    // ---- phase 3: pooled pair offsets (exclusive scan over 8 envs) ----
    if (tid == 0) {
        int a = 0;
        #pragma unroll
        for (int e = 0; e < EPB; e++) {
            eoff[e] = a;
            int n = ncnt[e];
            a += (n * (n - 1)) >> 1;
        }
        eoff[EPB] = a;
    }
    __syncthreads();

    // ---- phase 4a: radial — pooled (e, j, r) items, SMEM atomics ----
    #pragma unroll
    for (int k = 0; k < (EPB * AA * NSHFR) / NT; k++) {
        int t = tid + k * NT;                 // t & 15 == lane & 15 -> r matches shfr_r
        int e = t / (AA * NSHFR);
        int j = (t >> 4) - e * AA;
        float pr = spre[e][j];
        if (pr != 0.0f) {
            float u = sdd[e][j] - shfr_r;
            int   s = __float_as_int(atm[j].w);
            atomicAdd(&rad[e][s * NSHFR + (lane & 15)], pr * __expf(-etaR * u * u));
        }
    }

    // ---- phase 4b: angular — pooled pairs, warp-per-pair, 32 lanes = channels ----
    {
        // register copies of offsets and counts
        int off0 = eoff[0], off1 = eoff[1], off2 = eoff[2], off3 = eoff[3];
        int off4 = eoff[4], off5 = eoff[5], off6 = eoff[6], off7 = eoff[7];
        int P = eoff[EPB];

        for (int t = wid; t < P; t += NWARPS) {
            // env lookup: 8 compares (warp-uniform)
            int e = 0;
            e += (t >= off1); e += (t >= off2); e += (t >= off3); e += (t >= off4);
            e += (t >= off5); e += (t >= off6); e += (t >= off7);
            int ob;
            switch (e) {
                case 0: ob = off0; break; case 1: ob = off1; break;
                case 2: ob = off2; break; case 3: ob = off3; break;
                case 4: ob = off4; break; case 5: ob = off5; break;
                case 6: ob = off6; break; default: ob = off7; break;
            }
            int u = t - ob;
            int n = ncnt[e];
            // triangular decode: pair u -> (jj, kk), jj < kk < n
            float tn  = 2.0f * (float)n - 1.0f;
            int jj = (int)(0.5f * (tn - sqrtf(tn * tn - 8.0f * (float)u)));
            jj = max(0, min(jj, n - 2));
            int start = (jj * (2 * n - jj - 1)) >> 1;
            if (u < start) {
                jj--; start = (jj * (2 * n - jj - 1)) >> 1;
            } else if (u >= start + n - 1 - jj) {
                start += n - 1 - jj; jj++;
            }
            int kk = jj + 1 + (u - start);

            float4 aj = nbrA[e][jj];
            float4 ak = nbrA[e][kk];
            float2 bj = nbrB[e][jj];
            float2 bk = nbrB[e][kk];
            float c = 0.95f * (aj.x * ak.x + aj.y * ak.y + aj.z * ak.z);
            c = fminf(0.99f, fmaxf(-0.99f, c));
            float s    = sqrtf(1.0f - c * c);     // sin(arccos(c)) >= 0
            float davg = 0.5f * (aj.w + ak.w);
            float fcp2 = 2.0f * bj.x * bk.x;
            int   p    = s_triu[__float_as_int(bj.y) * NSPEC + __float_as_int(bk.y)];

            // cos(theta - ShfZ) = c*cosZ + sin(theta)*sinZ
            float base = 0.5f + 0.5f * (c * cz + s * sz);
            float f1;
            if (z32) {
                float b2 = base * base;
                float b4 = b2 * b2;
                float b8 = b4 * b4;
                float b16 = b8 * b8;
                f1 = b16 * b16;
            } else {
                f1 = __powf(base, zeta);
            }
            float uu = davg - sha;
            float f2 = __expf(-etaA * uu * uu);
            atomicAdd(&ang[e][p * 32 + lane], f1 * f2 * fcp2);
        }
    }
    __syncthreads();

    // ---- phase 5: write out 8 envs x 384 ----
    #pragma unroll
    for (int t = tid; t < EPB * OUTDIM; t += NT) {
        int e = t / OUTDIM;
        int o = t - e * OUTDIM;
        float v = (o < RADDIM) ? rad[e][o] : ang[e][o - RADDIM];
        out[(b * EPB + e) * OUTDIM + o] = v;
    }
}

extern "C" void kernel_launch(void* const* d_in, const int* in_sizes, int n_in,
                              void* d_out, int out_size)
{
    const float* coordsp = (const float*)d_in[0];
    const float* etaRp   = (const float*)d_in[1];
    const float* shfRp   = (const float*)d_in[2];
    const float* etaAp   = (const float*)d_in[3];
    const float* zetap   = (const float*)d_in[4];
    const float* shfAp   = (const float*)d_in[5];
    const float* shfZp   = (const float*)d_in[6];
    const int*   specp   = (const int*)d_in[7];
    const int*   triup   = (const int*)d_in[8];
    float*       outp    = (float*)d_out;

    aev_kernel<<<NBLK, NT>>>(coordsp, etaRp, shfRp, etaAp, zetap, shfAp,
                             shfZp, specp, triup, outp);
}